// round 10
// baseline (speedup 1.0000x reference)
#include <cuda_runtime.h>
#include <cstdint>
#include <cstddef>

#define TOKENS   131072
#define CDIM     96
#define NWIN     512
#define NTOK     256
#define HD       24
#define NHEADS   4
#define HIDDEN_DIM 384

typedef unsigned long long ull;

// Scratch (device globals)
__device__ float g_qkv [(size_t)3 * TOKENS * CDIM];
__device__ float g_attn[(size_t)TOKENS * CDIM];
__device__ float g_x2  [(size_t)TOKENS * CDIM];
__device__ float g_h   [(size_t)TOKENS * HIDDEN_DIM];

__device__ __forceinline__ int nat_index(int t) {
    int r = t & 255, w = t >> 8;
    int b = w >> 8, wi = w & 255;
    int d  = ((((wi >> 6) & 3) << 2) | ((r >> 6) & 3));
    int hh = ((((wi >> 4) & 3) << 2) | ((r >> 4) & 3));
    int ww = ((((wi >> 2) & 3) << 2) | ((r >> 2) & 3));
    int tt = (((wi & 3) << 2) | (r & 3));
    d = (d + 2) & 15; hh = (hh + 2) & 15; ww = (ww + 2) & 15; tt = (tt + 2) & 15;
    return (((b * 16 + d) * 16 + hh) * 16 + ww) * 16 + tt;
}

__device__ __forceinline__ int group_of(int wi, int r) {
    int g = 0;
#pragma unroll
    for (int a = 3; a >= 0; --a) {
        int c = ((((wi >> (2 * a)) & 3) << 2) | ((r >> (2 * a)) & 3));
        int s = (c < 12) ? 0 : ((c < 14) ? 1 : 2);
        g = g * 3 + s;
    }
    return g;
}

__device__ __forceinline__ void mma_tf32(float4& d, const uint32_t a[4], const uint32_t b[2]) {
    asm("mma.sync.aligned.m16n8k8.row.col.f32.tf32.tf32.f32 "
        "{%0,%1,%2,%3},{%4,%5,%6,%7},{%8,%9},{%0,%1,%2,%3};"
        : "+f"(d.x), "+f"(d.y), "+f"(d.z), "+f"(d.w)
        : "r"(a[0]), "r"(a[1]), "r"(a[2]), "r"(a[3]), "r"(b[0]), "r"(b[1]));
}

// cp.async helpers
__device__ __forceinline__ void cp16(uint32_t dst, const void* src) {
    asm volatile("cp.async.cg.shared.global [%0],[%1],16;" :: "r"(dst), "l"(src));
}
__device__ __forceinline__ void cp_commit() { asm volatile("cp.async.commit_group;"); }
template <int N>
__device__ __forceinline__ void cp_wait() { asm volatile("cp.async.wait_group %0;" :: "n"(N)); }

// Fast exact-enough GELU: erf via Abramowitz-Stegun 7.1.26 (|err| <= 1.5e-7).
__device__ __forceinline__ float gelu_f(float v) {
    float z = fabsf(v) * 0.70710678118654752f;
    float t = __frcp_rn(fmaf(0.3275911f, z, 1.f));
    float p = fmaf(fmaf(fmaf(fmaf(1.061405429f, t, -1.453152027f), t, 1.421413741f),
                        t, -0.284496736f), t, 0.254829592f) * t;
    float e = __expf(-z * z);
    float erf_abs = fmaf(-p, e, 1.f);
    float er = copysignf(erf_abs, v);
    return 0.5f * v * (1.f + er);
}

enum { EPI_QKV = 0, EPI_PROJ = 1, EPI_FC1 = 2, EPI_FC2 = 3 };

// ---------------------------------------------------------------------------
// A-resident tf32 GEMM; chunk loop FULLY UNROLLED (NC compile-time) so all
// stage parity / k-offset / swizzle arithmetic folds into LDS immediates.
// ---------------------------------------------------------------------------
#define ASTR2 100

template <int E, bool LNF, bool GATHER, int NB>
__global__ void __launch_bounds__(256, 2) gemm_fz(const float* __restrict__ A,
                                                  const float* __restrict__ W,
                                                  const float* __restrict__ bias,
                                                  const float* __restrict__ res,
                                                  const float* __restrict__ gamma,
                                                  const float* __restrict__ beta,
                                                  float* __restrict__ out) {
    extern __shared__ float smem[];
    float* As   = smem;
    float* ring = smem + 128 * ASTR2;
    constexpr int WCH = 96 * 32;
    constexpr int NC  = NB * 3;

    const int tid  = threadIdx.x;
    const int warp = tid >> 5, lane = tid & 31;
    const int gid  = lane >> 2, tig = lane & 3;
    const int wm   = (warp >> 1) * 32;
    const int wb   = warp & 1;
    const int wn   = wb * 48;
    const int m0   = blockIdx.x * 128;

    uint32_t as_u   = (uint32_t)__cvta_generic_to_shared(As);
    uint32_t ring_u = (uint32_t)__cvta_generic_to_shared(ring);

#pragma unroll
    for (int it = 0; it < 12; ++it) {
        int idx = tid + it * 256;
        int row = idx / 24, c4 = (idx % 24) << 2;
        int m = m0 + row;
        const float* src = A + (size_t)(GATHER ? nat_index(m) : m) * CDIM + c4;
        cp16(as_u + (row * ASTR2 + c4) * 4, src);
    }
    cp_commit();

    const int wrow = tid >> 3, wj = tid & 7;
    auto issueW = [&](int c) {
        uint32_t wbuf = ring_u + ((c & 1) * WCH) * 4;
        int n0 = (c / 3) * 96, kc = (c % 3) * 32;
#pragma unroll
        for (int it = 0; it < 3; ++it) {
            int r = wrow + it * 32;
            uint32_t dst = wbuf + (r * 32 + (((wj + r) & 7) << 2)) * 4;
            cp16(dst, W + (size_t)(n0 + r) * CDIM + kc + (wj << 2));
        }
    };
    issueW(0); cp_commit();

    if (LNF) {
        cp_wait<1>();
        __syncthreads();
        int row = tid >> 1, half = tid & 1;
        float s = 0.f, sq = 0.f;
#pragma unroll
        for (int i = 0; i < 48; ++i) {
            float v = As[row * ASTR2 + half * 48 + i];
            s += v; sq += v * v;
        }
        s  += __shfl_xor_sync(0xffffffffu, s, 1);
        sq += __shfl_xor_sync(0xffffffffu, sq, 1);
        float mean = s * (1.f / 96.f);
        float var  = sq * (1.f / 96.f) - mean * mean;
        float rstd = rsqrtf(var + 1e-5f);
#pragma unroll
        for (int i = 0; i < 48; ++i) {
            int col = half * 48 + i;
            As[row * ASTR2 + col] = (As[row * ASTR2 + col] - mean) * rstd * __ldg(gamma + col) + __ldg(beta + col);
        }
        __syncthreads();
    }

    const uint32_t* Asu = (const uint32_t*)As;

    float4 acc[2][6];
#pragma unroll
    for (int i = 0; i < 2; ++i)
#pragma unroll
        for (int j = 0; j < 6; ++j) acc[i][j] = make_float4(0.f, 0.f, 0.f, 0.f);

#pragma unroll
    for (int c = 0; c < NC; ++c) {
        if (c + 1 < NC) issueW(c + 1);
        cp_commit();
        cp_wait<1>();
        __syncthreads();

        const uint32_t* Ws = (const uint32_t*)(ring + (c & 1) * WCH);

#pragma unroll
        for (int ks4 = 0; ks4 < 4; ++ks4) {
            const int kg = (c % 3) * 32 + ks4 * 8;
            uint32_t a[2][4];
#pragma unroll
            for (int mi = 0; mi < 2; ++mi) {
                int r = wm + mi * 16 + gid;
                a[mi][0] = Asu[r * ASTR2 + kg + tig];
                a[mi][1] = Asu[(r + 8) * ASTR2 + kg + tig];
                a[mi][2] = Asu[r * ASTR2 + kg + tig + 4];
                a[mi][3] = Asu[(r + 8) * ASTR2 + kg + tig + 4];
            }
            uint32_t b[6][2];
#pragma unroll
            for (int ni = 0; ni < 6; ++ni) {
                int n = wn + ni * 8 + gid;
                int ch0 = (2 * ks4 + gid) & 7;
                int ch1 = (2 * ks4 + 1 + gid) & 7;
                b[ni][0] = Ws[n * 32 + (ch0 << 2) + tig];
                b[ni][1] = Ws[n * 32 + (ch1 << 2) + tig];
            }
#pragma unroll
            for (int mi = 0; mi < 2; ++mi)
#pragma unroll
                for (int ni = 0; ni < 6; ++ni) mma_tf32(acc[mi][ni], a[mi], b[ni]);
        }

        if ((c % 3) == 2) {
            const int nb = c / 3, n0 = nb * 96;
#pragma unroll
            for (int mi = 0; mi < 2; ++mi) {
                int r0 = m0 + wm + mi * 16 + gid;
#pragma unroll
                for (int half = 0; half < 2; ++half) {
                    int m = r0 + half * 8;
                    size_t proj_dst = 0;
                    if (E == EPI_PROJ) proj_dst = (size_t)nat_index(m) * CDIM;
                    int w = m >> 8, rr = m & 255;
#pragma unroll
                    for (int ni = 0; ni < 6; ++ni) {
                        float v0 = half ? acc[mi][ni].z : acc[mi][ni].x;
                        float v1 = half ? acc[mi][ni].w : acc[mi][ni].y;
#pragma unroll
                        for (int e = 0; e < 2; ++e) {
                            int nl = wn + ni * 8 + tig * 2 + e;
                            float v = (e ? v1 : v0) + bias[n0 + nl];
                            if (E == EPI_QKV) {
                                const float scale = (nb == 0) ? 0.20412414523193154f : 1.0f;
                                int h = nl / 24, dd = nl % 24;
                                out[(((size_t)nb * NWIN + w) * NHEADS + h) * (NTOK * HD) + rr * HD + dd] = v * scale;
                            } else if (E == EPI_PROJ) {
                                out[proj_dst + nl] = res[proj_dst + nl] + v;
                            } else if (E == EPI_FC1) {
                                out[(size_t)m * HIDDEN_DIM + n0 + nl] = gelu_f(v);
                            } else {
                                out[(size_t)m * CDIM + nl] = res[(size_t)m * CDIM + nl] + v;
                            }
                        }
                    }
                }
            }
            if (c + 1 < NC) {
#pragma unroll
                for (int i = 0; i < 2; ++i)
#pragma unroll
                    for (int j = 0; j < 6; ++j) acc[i][j] = make_float4(0.f, 0.f, 0.f, 0.f);
            }
        }
        __syncthreads();
    }
}

// ---------------------------------------------------------------------------
// Streaming tf32 GEMM for fc2 (K=384); chunk loop fully unrolled.
// ---------------------------------------------------------------------------
#define ASTR 36

__global__ void __launch_bounds__(256, 2) gemm_fc2(const float* __restrict__ A,
                                                   const float* __restrict__ W,
                                                   const float* __restrict__ bias,
                                                   const float* __restrict__ res,
                                                   float* __restrict__ out) {
    extern __shared__ float smem[];
    constexpr int ACH = 128 * ASTR, WCH = 96 * 32, STG = ACH + WCH;
    constexpr int KD = HIDDEN_DIM, NC = KD / 32, NSTG = 3, PF = 2;

    const int tid  = threadIdx.x;
    const int warp = tid >> 5, lane = tid & 31;
    const int gid  = lane >> 2, tig = lane & 3;
    const int wm   = (warp >> 1) * 32;
    const int wb   = warp & 1;
    const int wn   = wb * 48;
    const int m0   = blockIdx.x * 128;

    uint32_t smem_u = (uint32_t)__cvta_generic_to_shared(smem);
    const int crow = tid >> 3, cj = tid & 7, cc4 = cj << 2;

    auto issue = [&](int c) {
        int s = c % NSTG, kc = c * 32;
        uint32_t abuf = smem_u + (s * STG) * 4;
#pragma unroll
        for (int it = 0; it < 4; ++it) {
            int row = crow + it * 32;
            cp16(abuf + (row * ASTR + cc4) * 4, A + (size_t)(m0 + row) * KD + kc + cc4);
        }
        uint32_t wbuf = abuf + ACH * 4;
#pragma unroll
        for (int it = 0; it < 3; ++it) {
            int r = crow + it * 32;
            cp16(wbuf + (r * 32 + (((cj + r) & 7) << 2)) * 4,
                 W + (size_t)r * KD + kc + cc4);
        }
    };

    issue(0); cp_commit();
    issue(1); cp_commit();

    float4 acc[2][6];
#pragma unroll
    for (int i = 0; i < 2; ++i)
#pragma unroll
        for (int j = 0; j < 6; ++j) acc[i][j] = make_float4(0.f, 0.f, 0.f, 0.f);

#pragma unroll
    for (int c = 0; c < NC; ++c) {
        if (c + PF < NC) issue(c + PF);
        cp_commit();
        cp_wait<PF>();
        __syncthreads();

        const uint32_t* As = (const uint32_t*)(smem + (c % NSTG) * STG);
        const uint32_t* Ws = (const uint32_t*)(smem + (c % NSTG) * STG + ACH);

#pragma unroll
        for (int ks4 = 0; ks4 < 4; ++ks4) {
            const int k = ks4 * 8;
            uint32_t a[2][4];
#pragma unroll
            for (int mi = 0; mi < 2; ++mi) {
                int r = wm + mi * 16 + gid;
                a[mi][0] = As[r * ASTR + k + tig];
                a[mi][1] = As[(r + 8) * ASTR + k + tig];
                a[mi][2] = As[r * ASTR + k + tig + 4];
                a[mi][3] = As[(r + 8) * ASTR + k + tig + 4];
            }
            uint32_t b[6][2];
#pragma unroll
            for (int ni = 0; ni < 6; ++ni) {
                int n = wn + ni * 8 + gid;
                int ch0 = (2 * ks4 + gid) & 7;
                int ch1 = (2 * ks4 + 1 + gid) & 7;
                b[ni][0] = Ws[n * 32 + (ch0 << 2) + tig];
                b[ni][1] = Ws[n * 32 + (ch1 << 2) + tig];
            }
#pragma unroll
            for (int mi = 0; mi < 2; ++mi)
#pragma unroll
                for (int ni = 0; ni < 6; ++ni) mma_tf32(acc[mi][ni], a[mi], b[ni]);
        }
        __syncthreads();
    }

#pragma unroll
    for (int mi = 0; mi < 2; ++mi) {
        int r0 = m0 + wm + mi * 16 + gid;
#pragma unroll
        for (int half = 0; half < 2; ++half) {
            int m = r0 + half * 8;
#pragma unroll
            for (int ni = 0; ni < 6; ++ni) {
                float v0 = half ? acc[mi][ni].z : acc[mi][ni].x;
                float v1 = half ? acc[mi][ni].w : acc[mi][ni].y;
#pragma unroll
                for (int e = 0; e < 2; ++e) {
                    int nl = wn + ni * 8 + tig * 2 + e;
                    float v = (e ? v1 : v0) + bias[nl];
                    out[(size_t)m * CDIM + nl] = res[(size_t)m * CDIM + nl] + v;
                }
            }
        }
    }
}

// ---------------------------------------------------------------------------
// Tensor-core attention (unchanged from R9).
// ---------------------------------------------------------------------------
#define QSTR 28
#define PSTR 68

__global__ void __launch_bounds__(256) attn_mma(const float* __restrict__ qkv,
                                                float* __restrict__ attnout) {
    extern __shared__ float sm[];
    float* Qs = sm;
    float* Ks = Qs + 256 * QSTR;
    float* Vs = Ks + 256 * QSTR;
    float* Ps = Vs + 256 * 24;
    float* Ls = Ps + 256 * PSTR;
    unsigned char* grp = (unsigned char*)(Ls + 512);

    const int w = blockIdx.x, h = blockIdx.y;
    const int tid = threadIdx.x, warp = tid >> 5, lane = tid & 31;
    const int gid = lane >> 2, tig = lane & 3;
    const int wm = (warp >> 1) * 64;
    const int wb = warp & 1;
    const size_t hs = (size_t)NTOK * HD;
    const float* qb = qkv + (((size_t)0 * NWIN + w) * NHEADS + h) * hs;
    const float* kg = qkv + (((size_t)1 * NWIN + w) * NHEADS + h) * hs;
    const float* vg = qkv + (((size_t)2 * NWIN + w) * NHEADS + h) * hs;

#pragma unroll
    for (int it = 0; it < 6; ++it) {
        int idx = tid + it * 256;
        int row = idx / 6, c4 = (idx % 6) * 4;
        float4 q4 = *(const float4*)(qb + row * 24 + c4);
        float4 k4 = *(const float4*)(kg + row * 24 + c4);
        float4 v4 = *(const float4*)(vg + row * 24 + c4);
        Qs[row*QSTR+c4+0]=q4.x; Qs[row*QSTR+c4+1]=q4.y; Qs[row*QSTR+c4+2]=q4.z; Qs[row*QSTR+c4+3]=q4.w;
        Ks[row*QSTR+c4+0]=k4.x; Ks[row*QSTR+c4+1]=k4.y; Ks[row*QSTR+c4+2]=k4.z; Ks[row*QSTR+c4+3]=k4.w;
        *(float4*)(Vs + row * 24 + c4) = v4;
    }
    grp[tid] = (unsigned char)group_of(w & 255, tid);
    __syncthreads();

    const uint32_t* Qu = (const uint32_t*)Qs;
    const uint32_t* Ku = (const uint32_t*)Ks;
    const uint32_t* Vu = (const uint32_t*)Vs;
    const uint32_t* Pu = (const uint32_t*)Ps;

    float4 oacc[4][3];
#pragma unroll
    for (int i = 0; i < 4; ++i)
#pragma unroll
        for (int j = 0; j < 3; ++j) oacc[i][j] = make_float4(0.f, 0.f, 0.f, 0.f);
    float rs[4][2];
#pragma unroll
    for (int i = 0; i < 4; ++i) { rs[i][0] = 0.f; rs[i][1] = 0.f; }

    for (int kb = 0; kb < 4; ++kb) {
        float4 sacc[4][4];
#pragma unroll
        for (int i = 0; i < 4; ++i)
#pragma unroll
            for (int j = 0; j < 4; ++j) sacc[i][j] = make_float4(0.f, 0.f, 0.f, 0.f);

#pragma unroll
        for (int kk = 0; kk < 3; ++kk) {
            const int k8 = kk * 8;
            uint32_t a[4][4], b[4][2];
#pragma unroll
            for (int mi = 0; mi < 4; ++mi) {
                int r = wm + mi * 16 + gid;
                a[mi][0] = Qu[r * QSTR + k8 + tig];
                a[mi][1] = Qu[(r + 8) * QSTR + k8 + tig];
                a[mi][2] = Qu[r * QSTR + k8 + tig + 4];
                a[mi][3] = Qu[(r + 8) * QSTR + k8 + tig + 4];
            }
#pragma unroll
            for (int ni = 0; ni < 4; ++ni) {
                int n = kb * 64 + wb * 32 + ni * 8 + gid;
                b[ni][0] = Ku[n * QSTR + k8 + tig];
                b[ni][1] = Ku[n * QSTR + k8 + tig + 4];
            }
#pragma unroll
            for (int mi = 0; mi < 4; ++mi)
#pragma unroll
                for (int ni = 0; ni < 4; ++ni) mma_tf32(sacc[mi][ni], a[mi], b[ni]);
        }

#pragma unroll
        for (int mi = 0; mi < 4; ++mi) {
            int r0 = wm + mi * 16 + gid;
            int rg0 = grp[r0], rg1 = grp[r0 + 8];
#pragma unroll
            for (int ni = 0; ni < 4; ++ni) {
                int cc = kb * 64 + wb * 32 + ni * 8 + 2 * tig;
                int cg0 = grp[cc], cg1 = grp[cc + 1];
                float4 s = sacc[mi][ni];
                float p00 = __expf(s.x + (cg0 == rg0 ? 0.f : -100.f));
                float p01 = __expf(s.y + (cg1 == rg0 ? 0.f : -100.f));
                float p10 = __expf(s.z + (cg0 == rg1 ? 0.f : -100.f));
                float p11 = __expf(s.w + (cg1 == rg1 ? 0.f : -100.f));
                rs[mi][0] += p00 + p01;
                rs[mi][1] += p10 + p11;
                int pc = wb * 32 + ni * 8 + 2 * tig;
                *(float2*)(Ps + r0 * PSTR + pc)       = make_float2(p00, p01);
                *(float2*)(Ps + (r0 + 8) * PSTR + pc) = make_float2(p10, p11);
            }
        }
        __syncwarp();

#pragma unroll
        for (int kk = 0; kk < 4; ++kk) {
            const int kp = wb * 32 + kk * 8;
            const int kv = kb * 64 + kp;
            uint32_t a[4][4], b[3][2];
#pragma unroll
            for (int mi = 0; mi < 4; ++mi) {
                int r = wm + mi * 16 + gid;
                a[mi][0] = Pu[r * PSTR + kp + tig];
                a[mi][1] = Pu[(r + 8) * PSTR + kp + tig];
                a[mi][2] = Pu[r * PSTR + kp + tig + 4];
                a[mi][3] = Pu[(r + 8) * PSTR + kp + tig + 4];
            }
#pragma unroll
            for (int nd = 0; nd < 3; ++nd) {
                int n = nd * 8 + gid;
                b[nd][0] = Vu[(kv + tig) * 24 + n];
                b[nd][1] = Vu[(kv + tig + 4) * 24 + n];
            }
#pragma unroll
            for (int mi = 0; mi < 4; ++mi)
#pragma unroll
                for (int nd = 0; nd < 3; ++nd) mma_tf32(oacc[mi][nd], a[mi], b[nd]);
        }
        __syncwarp();
    }

#pragma unroll
    for (int mi = 0; mi < 4; ++mi)
#pragma unroll
        for (int hf = 0; hf < 2; ++hf) {
            float v = rs[mi][hf];
            v += __shfl_xor_sync(0xffffffffu, v, 1);
            v += __shfl_xor_sync(0xffffffffu, v, 2);
            rs[mi][hf] = v;
        }
    if (tig == 0) {
#pragma unroll
        for (int mi = 0; mi < 4; ++mi) {
            Ls[wb * 256 + wm + mi * 16 + gid]     = rs[mi][0];
            Ls[wb * 256 + wm + mi * 16 + gid + 8] = rs[mi][1];
        }
    }
    __syncthreads();

    float* OS = Qs;
    const int OSTR = 26;
    if (wb == 1) {
#pragma unroll
        for (int mi = 0; mi < 4; ++mi) {
            int r0 = wm + mi * 16 + gid;
#pragma unroll
            for (int nd = 0; nd < 3; ++nd) {
                int c = nd * 8 + 2 * tig;
                *(float2*)(OS + r0 * OSTR + c)       = make_float2(oacc[mi][nd].x, oacc[mi][nd].y);
                *(float2*)(OS + (r0 + 8) * OSTR + c) = make_float2(oacc[mi][nd].z, oacc[mi][nd].w);
            }
        }
    }
    __syncthreads();
    if (wb == 0) {
#pragma unroll
        for (int mi = 0; mi < 4; ++mi) {
            int r0 = wm + mi * 16 + gid, r1 = r0 + 8;
            float inv0 = 1.f / (Ls[r0] + Ls[256 + r0]);
            float inv1 = 1.f / (Ls[r1] + Ls[256 + r1]);
#pragma unroll
            for (int nd = 0; nd < 3; ++nd) {
                int c = nd * 8 + 2 * tig;
                float2 t0 = *(float2*)(OS + r0 * OSTR + c);
                float2 t1 = *(float2*)(OS + r1 * OSTR + c);
                float* o0 = attnout + ((size_t)w * NTOK + r0) * CDIM + h * HD + c;
                float* o1 = attnout + ((size_t)w * NTOK + r1) * CDIM + h * HD + c;
                o0[0] = (oacc[mi][nd].x + t0.x) * inv0;
                o0[1] = (oacc[mi][nd].y + t0.y) * inv0;
                o1[0] = (oacc[mi][nd].z + t1.x) * inv1;
                o1[1] = (oacc[mi][nd].w + t1.y) * inv1;
            }
        }
    }
}

// ---------------------------------------------------------------------------
extern "C" void kernel_launch(void* const* d_in, const int* in_sizes, int n_in,
                              void* d_out, int out_size) {
    (void)in_sizes; (void)n_in; (void)out_size;
    const float* x       = (const float*)d_in[0];
    const float* norm1_g = (const float*)d_in[2];
    const float* norm1_b = (const float*)d_in[3];
    const float* qkv_w   = (const float*)d_in[4];
    const float* qkv_b   = (const float*)d_in[5];
    const float* proj_w  = (const float*)d_in[6];
    const float* proj_b  = (const float*)d_in[7];
    const float* norm2_g = (const float*)d_in[8];
    const float* norm2_b = (const float*)d_in[9];
    const float* fc1_w   = (const float*)d_in[10];
    const float* fc1_b   = (const float*)d_in[11];
    const float* fc2_w   = (const float*)d_in[12];
    const float* fc2_b   = (const float*)d_in[13];
    float* out = (float*)d_out;

    float *qkv, *attn, *x2, *hbuf;
    cudaGetSymbolAddress((void**)&qkv,  g_qkv);
    cudaGetSymbolAddress((void**)&attn, g_attn);
    cudaGetSymbolAddress((void**)&x2,   g_x2);
    cudaGetSymbolAddress((void**)&hbuf, g_h);

    const int fz_smem  = (128 * ASTR2 + 2 * 96 * 32) * 4;
    const int fc2_smem = 3 * (128 * ASTR + 96 * 32) * 4;
    cudaFuncSetAttribute(gemm_fz<EPI_QKV,  true,  true,  3>, cudaFuncAttributeMaxDynamicSharedMemorySize, fz_smem);
    cudaFuncSetAttribute(gemm_fz<EPI_PROJ, false, false, 1>, cudaFuncAttributeMaxDynamicSharedMemorySize, fz_smem);
    cudaFuncSetAttribute(gemm_fz<EPI_FC1,  true,  false, 4>, cudaFuncAttributeMaxDynamicSharedMemorySize, fz_smem);
    cudaFuncSetAttribute(gemm_fc2, cudaFuncAttributeMaxDynamicSharedMemorySize, fc2_smem);

    const int attn_smem = (256 * QSTR * 2 + 256 * 24 + 256 * PSTR + 512 + 64) * 4;
    cudaFuncSetAttribute(attn_mma, cudaFuncAttributeMaxDynamicSharedMemorySize, attn_smem);

    gemm_fz<EPI_QKV, true, true, 3><<<1024, 256, fz_smem>>>(
        x, qkv_w, qkv_b, nullptr, norm1_g, norm1_b, qkv);
    attn_mma<<<dim3(NWIN, NHEADS), 256, attn_smem>>>(qkv, attn);
    gemm_fz<EPI_PROJ, false, false, 1><<<1024, 256, fz_smem>>>(
        attn, proj_w, proj_b, x, nullptr, nullptr, x2);
    gemm_fz<EPI_FC1, true, false, 4><<<1024, 256, fz_smem>>>(
        x2, fc1_w, fc1_b, nullptr, norm2_g, norm2_b, hbuf);
    gemm_fc2<<<1024, 256, fc2_smem>>>(hbuf, fc2_w, fc2_b, x2, out);
}

// round 11
// speedup vs baseline: 1.0470x; 1.0470x over previous
#include <cuda_runtime.h>
#include <cstdint>
#include <cstddef>

#define TOKENS   131072
#define CDIM     96
#define NWIN     512
#define NTOK     256
#define HD       24
#define NHEADS   4
#define HIDDEN_DIM 384

typedef unsigned long long ull;

// Scratch (device globals)
__device__ float g_qkv [(size_t)3 * TOKENS * CDIM];
__device__ float g_attn[(size_t)TOKENS * CDIM];
__device__ float g_x2  [(size_t)TOKENS * CDIM];
__device__ float g_h   [(size_t)TOKENS * HIDDEN_DIM];

__device__ __forceinline__ int nat_index(int t) {
    int r = t & 255, w = t >> 8;
    int b = w >> 8, wi = w & 255;
    int d  = ((((wi >> 6) & 3) << 2) | ((r >> 6) & 3));
    int hh = ((((wi >> 4) & 3) << 2) | ((r >> 4) & 3));
    int ww = ((((wi >> 2) & 3) << 2) | ((r >> 2) & 3));
    int tt = (((wi & 3) << 2) | (r & 3));
    d = (d + 2) & 15; hh = (hh + 2) & 15; ww = (ww + 2) & 15; tt = (tt + 2) & 15;
    return (((b * 16 + d) * 16 + hh) * 16 + ww) * 16 + tt;
}

__device__ __forceinline__ int group_of(int wi, int r) {
    int g = 0;
#pragma unroll
    for (int a = 3; a >= 0; --a) {
        int c = ((((wi >> (2 * a)) & 3) << 2) | ((r >> (2 * a)) & 3));
        int s = (c < 12) ? 0 : ((c < 14) ? 1 : 2);
        g = g * 3 + s;
    }
    return g;
}

__device__ __forceinline__ void mma_tf32(float4& d, const uint32_t a[4], const uint32_t b[2]) {
    asm("mma.sync.aligned.m16n8k8.row.col.f32.tf32.tf32.f32 "
        "{%0,%1,%2,%3},{%4,%5,%6,%7},{%8,%9},{%0,%1,%2,%3};"
        : "+f"(d.x), "+f"(d.y), "+f"(d.z), "+f"(d.w)
        : "r"(a[0]), "r"(a[1]), "r"(a[2]), "r"(a[3]), "r"(b[0]), "r"(b[1]));
}

// cp.async helpers
__device__ __forceinline__ void cp16(uint32_t dst, const void* src) {
    asm volatile("cp.async.cg.shared.global [%0],[%1],16;" :: "r"(dst), "l"(src));
}
__device__ __forceinline__ void cp_commit() { asm volatile("cp.async.commit_group;"); }
template <int N>
__device__ __forceinline__ void cp_wait() { asm volatile("cp.async.wait_group %0;" :: "n"(N)); }

// Fast exact-enough GELU: erf via Abramowitz-Stegun 7.1.26 (|err| <= 1.5e-7).
__device__ __forceinline__ float gelu_f(float v) {
    float z = fabsf(v) * 0.70710678118654752f;
    float t = __frcp_rn(fmaf(0.3275911f, z, 1.f));
    float p = fmaf(fmaf(fmaf(fmaf(1.061405429f, t, -1.453152027f), t, 1.421413741f),
                        t, -0.284496736f), t, 0.254829592f) * t;
    float e = __expf(-z * z);
    float erf_abs = fmaf(-p, e, 1.f);
    float er = copysignf(erf_abs, v);
    return 0.5f * v * (1.f + er);
}

enum { EPI_QKV = 0, EPI_PROJ = 1, EPI_FC1 = 2, EPI_FC2 = 3 };

// ---------------------------------------------------------------------------
// A-resident tf32 GEMM (R9 structure: runtime chunk loop, compact body).
// ---------------------------------------------------------------------------
#define ASTR2 100

template <int E, bool LNF, bool GATHER, int NB>
__global__ void __launch_bounds__(256, 2) gemm_fz(const float* __restrict__ A,
                                                  const float* __restrict__ W,
                                                  const float* __restrict__ bias,
                                                  const float* __restrict__ res,
                                                  const float* __restrict__ gamma,
                                                  const float* __restrict__ beta,
                                                  float* __restrict__ out) {
    extern __shared__ float smem[];
    float* As   = smem;
    float* ring = smem + 128 * ASTR2;
    constexpr int WCH = 96 * 32;
    constexpr int NC  = NB * 3;

    const int tid  = threadIdx.x;
    const int warp = tid >> 5, lane = tid & 31;
    const int gid  = lane >> 2, tig = lane & 3;
    const int wm   = (warp >> 1) * 32;
    const int wb   = warp & 1;
    const int wn   = wb * 48;
    const int m0   = blockIdx.x * 128;

    uint32_t as_u   = (uint32_t)__cvta_generic_to_shared(As);
    uint32_t ring_u = (uint32_t)__cvta_generic_to_shared(ring);

#pragma unroll
    for (int it = 0; it < 12; ++it) {
        int idx = tid + it * 256;
        int row = idx / 24, c4 = (idx % 24) << 2;
        int m = m0 + row;
        const float* src = A + (size_t)(GATHER ? nat_index(m) : m) * CDIM + c4;
        cp16(as_u + (row * ASTR2 + c4) * 4, src);
    }
    cp_commit();

    const int wrow = tid >> 3, wj = tid & 7;
    auto issueW = [&](int c) {
        uint32_t wbuf = ring_u + ((c & 1) * WCH) * 4;
        int n0 = (c / 3) * 96, kc = (c % 3) * 32;
#pragma unroll
        for (int it = 0; it < 3; ++it) {
            int r = wrow + it * 32;
            uint32_t dst = wbuf + (r * 32 + (((wj + r) & 7) << 2)) * 4;
            cp16(dst, W + (size_t)(n0 + r) * CDIM + kc + (wj << 2));
        }
    };
    issueW(0); cp_commit();

    if (LNF) {
        cp_wait<1>();
        __syncthreads();
        int row = tid >> 1, half = tid & 1;
        float s = 0.f, sq = 0.f;
#pragma unroll
        for (int i = 0; i < 48; ++i) {
            float v = As[row * ASTR2 + half * 48 + i];
            s += v; sq += v * v;
        }
        s  += __shfl_xor_sync(0xffffffffu, s, 1);
        sq += __shfl_xor_sync(0xffffffffu, sq, 1);
        float mean = s * (1.f / 96.f);
        float var  = sq * (1.f / 96.f) - mean * mean;
        float rstd = rsqrtf(var + 1e-5f);
#pragma unroll
        for (int i = 0; i < 48; ++i) {
            int col = half * 48 + i;
            As[row * ASTR2 + col] = (As[row * ASTR2 + col] - mean) * rstd * __ldg(gamma + col) + __ldg(beta + col);
        }
        __syncthreads();
    }

    const uint32_t* Asu = (const uint32_t*)As;

    float4 acc[2][6];
#pragma unroll
    for (int i = 0; i < 2; ++i)
#pragma unroll
        for (int j = 0; j < 6; ++j) acc[i][j] = make_float4(0.f, 0.f, 0.f, 0.f);

    for (int c = 0; c < NC; ++c) {
        if (c + 1 < NC) issueW(c + 1);
        cp_commit();
        cp_wait<1>();
        __syncthreads();

        const uint32_t* Ws = (const uint32_t*)(ring + (c & 1) * WCH);

#pragma unroll
        for (int ks4 = 0; ks4 < 4; ++ks4) {
            const int kg = (c % 3) * 32 + ks4 * 8;
            uint32_t a[2][4];
#pragma unroll
            for (int mi = 0; mi < 2; ++mi) {
                int r = wm + mi * 16 + gid;
                a[mi][0] = Asu[r * ASTR2 + kg + tig];
                a[mi][1] = Asu[(r + 8) * ASTR2 + kg + tig];
                a[mi][2] = Asu[r * ASTR2 + kg + tig + 4];
                a[mi][3] = Asu[(r + 8) * ASTR2 + kg + tig + 4];
            }
            uint32_t b[6][2];
#pragma unroll
            for (int ni = 0; ni < 6; ++ni) {
                int n = wn + ni * 8 + gid;
                int ch0 = (2 * ks4 + gid) & 7;
                int ch1 = (2 * ks4 + 1 + gid) & 7;
                b[ni][0] = Ws[n * 32 + (ch0 << 2) + tig];
                b[ni][1] = Ws[n * 32 + (ch1 << 2) + tig];
            }
#pragma unroll
            for (int mi = 0; mi < 2; ++mi)
#pragma unroll
                for (int ni = 0; ni < 6; ++ni) mma_tf32(acc[mi][ni], a[mi], b[ni]);
        }

        if ((c % 3) == 2) {
            const int nb = c / 3, n0 = nb * 96;
#pragma unroll
            for (int mi = 0; mi < 2; ++mi) {
                int r0 = m0 + wm + mi * 16 + gid;
#pragma unroll
                for (int half = 0; half < 2; ++half) {
                    int m = r0 + half * 8;
                    size_t proj_dst = 0;
                    if (E == EPI_PROJ) proj_dst = (size_t)nat_index(m) * CDIM;
                    int w = m >> 8, rr = m & 255;
#pragma unroll
                    for (int ni = 0; ni < 6; ++ni) {
                        float v0 = half ? acc[mi][ni].z : acc[mi][ni].x;
                        float v1 = half ? acc[mi][ni].w : acc[mi][ni].y;
#pragma unroll
                        for (int e = 0; e < 2; ++e) {
                            int nl = wn + ni * 8 + tig * 2 + e;
                            float v = (e ? v1 : v0) + bias[n0 + nl];
                            if (E == EPI_QKV) {
                                const float scale = (nb == 0) ? 0.20412414523193154f : 1.0f;
                                int h = nl / 24, dd = nl % 24;
                                out[(((size_t)nb * NWIN + w) * NHEADS + h) * (NTOK * HD) + rr * HD + dd] = v * scale;
                            } else if (E == EPI_PROJ) {
                                out[proj_dst + nl] = res[proj_dst + nl] + v;
                            } else if (E == EPI_FC1) {
                                out[(size_t)m * HIDDEN_DIM + n0 + nl] = gelu_f(v);
                            } else {
                                out[(size_t)m * CDIM + nl] = res[(size_t)m * CDIM + nl] + v;
                            }
                        }
                    }
                }
            }
            if (c + 1 < NC) {
#pragma unroll
                for (int i = 0; i < 2; ++i)
#pragma unroll
                    for (int j = 0; j < 6; ++j) acc[i][j] = make_float4(0.f, 0.f, 0.f, 0.f);
            }
        }
        __syncthreads();
    }
}

// ---------------------------------------------------------------------------
// Streaming tf32 GEMM for fc2 (K=384), runtime chunk loop (R9 structure).
// ---------------------------------------------------------------------------
#define ASTR 36

__global__ void __launch_bounds__(256, 2) gemm_fc2(const float* __restrict__ A,
                                                   const float* __restrict__ W,
                                                   const float* __restrict__ bias,
                                                   const float* __restrict__ res,
                                                   float* __restrict__ out) {
    extern __shared__ float smem[];
    constexpr int ACH = 128 * ASTR, WCH = 96 * 32, STG = ACH + WCH;
    constexpr int KD = HIDDEN_DIM, NC = KD / 32, NSTG = 3, PF = 2;

    const int tid  = threadIdx.x;
    const int warp = tid >> 5, lane = tid & 31;
    const int gid  = lane >> 2, tig = lane & 3;
    const int wm   = (warp >> 1) * 32;
    const int wb   = warp & 1;
    const int wn   = wb * 48;
    const int m0   = blockIdx.x * 128;

    uint32_t smem_u = (uint32_t)__cvta_generic_to_shared(smem);
    const int crow = tid >> 3, cj = tid & 7, cc4 = cj << 2;

    auto issue = [&](int c) {
        int s = c % NSTG, kc = c * 32;
        uint32_t abuf = smem_u + (s * STG) * 4;
#pragma unroll
        for (int it = 0; it < 4; ++it) {
            int row = crow + it * 32;
            cp16(abuf + (row * ASTR + cc4) * 4, A + (size_t)(m0 + row) * KD + kc + cc4);
        }
        uint32_t wbuf = abuf + ACH * 4;
#pragma unroll
        for (int it = 0; it < 3; ++it) {
            int r = crow + it * 32;
            cp16(wbuf + (r * 32 + (((cj + r) & 7) << 2)) * 4,
                 W + (size_t)r * KD + kc + cc4);
        }
    };

    issue(0); cp_commit();
    issue(1); cp_commit();

    float4 acc[2][6];
#pragma unroll
    for (int i = 0; i < 2; ++i)
#pragma unroll
        for (int j = 0; j < 6; ++j) acc[i][j] = make_float4(0.f, 0.f, 0.f, 0.f);

    for (int c = 0; c < NC; ++c) {
        if (c + PF < NC) issue(c + PF);
        cp_commit();
        cp_wait<PF>();
        __syncthreads();

        const uint32_t* As = (const uint32_t*)(smem + (c % NSTG) * STG);
        const uint32_t* Ws = (const uint32_t*)(smem + (c % NSTG) * STG + ACH);

#pragma unroll
        for (int ks4 = 0; ks4 < 4; ++ks4) {
            const int k = ks4 * 8;
            uint32_t a[2][4];
#pragma unroll
            for (int mi = 0; mi < 2; ++mi) {
                int r = wm + mi * 16 + gid;
                a[mi][0] = As[r * ASTR + k + tig];
                a[mi][1] = As[(r + 8) * ASTR + k + tig];
                a[mi][2] = As[r * ASTR + k + tig + 4];
                a[mi][3] = As[(r + 8) * ASTR + k + tig + 4];
            }
            uint32_t b[6][2];
#pragma unroll
            for (int ni = 0; ni < 6; ++ni) {
                int n = wn + ni * 8 + gid;
                int ch0 = (2 * ks4 + gid) & 7;
                int ch1 = (2 * ks4 + 1 + gid) & 7;
                b[ni][0] = Ws[n * 32 + (ch0 << 2) + tig];
                b[ni][1] = Ws[n * 32 + (ch1 << 2) + tig];
            }
#pragma unroll
            for (int mi = 0; mi < 2; ++mi)
#pragma unroll
                for (int ni = 0; ni < 6; ++ni) mma_tf32(acc[mi][ni], a[mi], b[ni]);
        }
        __syncthreads();
    }

#pragma unroll
    for (int mi = 0; mi < 2; ++mi) {
        int r0 = m0 + wm + mi * 16 + gid;
#pragma unroll
        for (int half = 0; half < 2; ++half) {
            int m = r0 + half * 8;
#pragma unroll
            for (int ni = 0; ni < 6; ++ni) {
                float v0 = half ? acc[mi][ni].z : acc[mi][ni].x;
                float v1 = half ? acc[mi][ni].w : acc[mi][ni].y;
#pragma unroll
                for (int e = 0; e < 2; ++e) {
                    int nl = wn + ni * 8 + tig * 2 + e;
                    float v = (e ? v1 : v0) + bias[nl];
                    out[(size_t)m * CDIM + nl] = res[(size_t)m * CDIM + nl] + v;
                }
            }
        }
    }
}

// ---------------------------------------------------------------------------
// Tensor-core attention (unchanged from R9).
// ---------------------------------------------------------------------------
#define QSTR 28
#define PSTR 68

__global__ void __launch_bounds__(256) attn_mma(const float* __restrict__ qkv,
                                                float* __restrict__ attnout) {
    extern __shared__ float sm[];
    float* Qs = sm;
    float* Ks = Qs + 256 * QSTR;
    float* Vs = Ks + 256 * QSTR;
    float* Ps = Vs + 256 * 24;
    float* Ls = Ps + 256 * PSTR;
    unsigned char* grp = (unsigned char*)(Ls + 512);

    const int w = blockIdx.x, h = blockIdx.y;
    const int tid = threadIdx.x, warp = tid >> 5, lane = tid & 31;
    const int gid = lane >> 2, tig = lane & 3;
    const int wm = (warp >> 1) * 64;
    const int wb = warp & 1;
    const size_t hs = (size_t)NTOK * HD;
    const float* qb = qkv + (((size_t)0 * NWIN + w) * NHEADS + h) * hs;
    const float* kg = qkv + (((size_t)1 * NWIN + w) * NHEADS + h) * hs;
    const float* vg = qkv + (((size_t)2 * NWIN + w) * NHEADS + h) * hs;

#pragma unroll
    for (int it = 0; it < 6; ++it) {
        int idx = tid + it * 256;
        int row = idx / 6, c4 = (idx % 6) * 4;
        float4 q4 = *(const float4*)(qb + row * 24 + c4);
        float4 k4 = *(const float4*)(kg + row * 24 + c4);
        float4 v4 = *(const float4*)(vg + row * 24 + c4);
        Qs[row*QSTR+c4+0]=q4.x; Qs[row*QSTR+c4+1]=q4.y; Qs[row*QSTR+c4+2]=q4.z; Qs[row*QSTR+c4+3]=q4.w;
        Ks[row*QSTR+c4+0]=k4.x; Ks[row*QSTR+c4+1]=k4.y; Ks[row*QSTR+c4+2]=k4.z; Ks[row*QSTR+c4+3]=k4.w;
        *(float4*)(Vs + row * 24 + c4) = v4;
    }
    grp[tid] = (unsigned char)group_of(w & 255, tid);
    __syncthreads();

    const uint32_t* Qu = (const uint32_t*)Qs;
    const uint32_t* Ku = (const uint32_t*)Ks;
    const uint32_t* Vu = (const uint32_t*)Vs;
    const uint32_t* Pu = (const uint32_t*)Ps;

    float4 oacc[4][3];
#pragma unroll
    for (int i = 0; i < 4; ++i)
#pragma unroll
        for (int j = 0; j < 3; ++j) oacc[i][j] = make_float4(0.f, 0.f, 0.f, 0.f);
    float rs[4][2];
#pragma unroll
    for (int i = 0; i < 4; ++i) { rs[i][0] = 0.f; rs[i][1] = 0.f; }

    for (int kb = 0; kb < 4; ++kb) {
        float4 sacc[4][4];
#pragma unroll
        for (int i = 0; i < 4; ++i)
#pragma unroll
            for (int j = 0; j < 4; ++j) sacc[i][j] = make_float4(0.f, 0.f, 0.f, 0.f);

#pragma unroll
        for (int kk = 0; kk < 3; ++kk) {
            const int k8 = kk * 8;
            uint32_t a[4][4], b[4][2];
#pragma unroll
            for (int mi = 0; mi < 4; ++mi) {
                int r = wm + mi * 16 + gid;
                a[mi][0] = Qu[r * QSTR + k8 + tig];
                a[mi][1] = Qu[(r + 8) * QSTR + k8 + tig];
                a[mi][2] = Qu[r * QSTR + k8 + tig + 4];
                a[mi][3] = Qu[(r + 8) * QSTR + k8 + tig + 4];
            }
#pragma unroll
            for (int ni = 0; ni < 4; ++ni) {
                int n = kb * 64 + wb * 32 + ni * 8 + gid;
                b[ni][0] = Ku[n * QSTR + k8 + tig];
                b[ni][1] = Ku[n * QSTR + k8 + tig + 4];
            }
#pragma unroll
            for (int mi = 0; mi < 4; ++mi)
#pragma unroll
                for (int ni = 0; ni < 4; ++ni) mma_tf32(sacc[mi][ni], a[mi], b[ni]);
        }

#pragma unroll
        for (int mi = 0; mi < 4; ++mi) {
            int r0 = wm + mi * 16 + gid;
            int rg0 = grp[r0], rg1 = grp[r0 + 8];
#pragma unroll
            for (int ni = 0; ni < 4; ++ni) {
                int cc = kb * 64 + wb * 32 + ni * 8 + 2 * tig;
                int cg0 = grp[cc], cg1 = grp[cc + 1];
                float4 s = sacc[mi][ni];
                float p00 = __expf(s.x + (cg0 == rg0 ? 0.f : -100.f));
                float p01 = __expf(s.y + (cg1 == rg0 ? 0.f : -100.f));
                float p10 = __expf(s.z + (cg0 == rg1 ? 0.f : -100.f));
                float p11 = __expf(s.w + (cg1 == rg1 ? 0.f : -100.f));
                rs[mi][0] += p00 + p01;
                rs[mi][1] += p10 + p11;
                int pc = wb * 32 + ni * 8 + 2 * tig;
                *(float2*)(Ps + r0 * PSTR + pc)       = make_float2(p00, p01);
                *(float2*)(Ps + (r0 + 8) * PSTR + pc) = make_float2(p10, p11);
            }
        }
        __syncwarp();

#pragma unroll
        for (int kk = 0; kk < 4; ++kk) {
            const int kp = wb * 32 + kk * 8;
            const int kv = kb * 64 + kp;
            uint32_t a[4][4], b[3][2];
#pragma unroll
            for (int mi = 0; mi < 4; ++mi) {
                int r = wm + mi * 16 + gid;
                a[mi][0] = Pu[r * PSTR + kp + tig];
                a[mi][1] = Pu[(r + 8) * PSTR + kp + tig];
                a[mi][2] = Pu[r * PSTR + kp + tig + 4];
                a[mi][3] = Pu[(r + 8) * PSTR + kp + tig + 4];
            }
#pragma unroll
            for (int nd = 0; nd < 3; ++nd) {
                int n = nd * 8 + gid;
                b[nd][0] = Vu[(kv + tig) * 24 + n];
                b[nd][1] = Vu[(kv + tig + 4) * 24 + n];
            }
#pragma unroll
            for (int mi = 0; mi < 4; ++mi)
#pragma unroll
                for (int nd = 0; nd < 3; ++nd) mma_tf32(oacc[mi][nd], a[mi], b[nd]);
        }
        __syncwarp();
    }

#pragma unroll
    for (int mi = 0; mi < 4; ++mi)
#pragma unroll
        for (int hf = 0; hf < 2; ++hf) {
            float v = rs[mi][hf];
            v += __shfl_xor_sync(0xffffffffu, v, 1);
            v += __shfl_xor_sync(0xffffffffu, v, 2);
            rs[mi][hf] = v;
        }
    if (tig == 0) {
#pragma unroll
        for (int mi = 0; mi < 4; ++mi) {
            Ls[wb * 256 + wm + mi * 16 + gid]     = rs[mi][0];
            Ls[wb * 256 + wm + mi * 16 + gid + 8] = rs[mi][1];
        }
    }
    __syncthreads();

    float* OS = Qs;
    const int OSTR = 26;
    if (wb == 1) {
#pragma unroll
        for (int mi = 0; mi < 4; ++mi) {
            int r0 = wm + mi * 16 + gid;
#pragma unroll
            for (int nd = 0; nd < 3; ++nd) {
                int c = nd * 8 + 2 * tig;
                *(float2*)(OS + r0 * OSTR + c)       = make_float2(oacc[mi][nd].x, oacc[mi][nd].y);
                *(float2*)(OS + (r0 + 8) * OSTR + c) = make_float2(oacc[mi][nd].z, oacc[mi][nd].w);
            }
        }
    }
    __syncthreads();
    if (wb == 0) {
#pragma unroll
        for (int mi = 0; mi < 4; ++mi) {
            int r0 = wm + mi * 16 + gid, r1 = r0 + 8;
            float inv0 = 1.f / (Ls[r0] + Ls[256 + r0]);
            float inv1 = 1.f / (Ls[r1] + Ls[256 + r1]);
#pragma unroll
            for (int nd = 0; nd < 3; ++nd) {
                int c = nd * 8 + 2 * tig;
                float2 t0 = *(float2*)(OS + r0 * OSTR + c);
                float2 t1 = *(float2*)(OS + r1 * OSTR + c);
                float* o0 = attnout + ((size_t)w * NTOK + r0) * CDIM + h * HD + c;
                float* o1 = attnout + ((size_t)w * NTOK + r1) * CDIM + h * HD + c;
                o0[0] = (oacc[mi][nd].x + t0.x) * inv0;
                o0[1] = (oacc[mi][nd].y + t0.y) * inv0;
                o1[0] = (oacc[mi][nd].z + t1.x) * inv1;
                o1[1] = (oacc[mi][nd].w + t1.y) * inv1;
            }
        }
    }
}

// ---------------------------------------------------------------------------
extern "C" void kernel_launch(void* const* d_in, const int* in_sizes, int n_in,
                              void* d_out, int out_size) {
    (void)in_sizes; (void)n_in; (void)out_size;
    const float* x       = (const float*)d_in[0];
    const float* norm1_g = (const float*)d_in[2];
    const float* norm1_b = (const float*)d_in[3];
    const float* qkv_w   = (const float*)d_in[4];
    const float* qkv_b   = (const float*)d_in[5];
    const float* proj_w  = (const float*)d_in[6];
    const float* proj_b  = (const float*)d_in[7];
    const float* norm2_g = (const float*)d_in[8];
    const float* norm2_b = (const float*)d_in[9];
    const float* fc1_w   = (const float*)d_in[10];
    const float* fc1_b   = (const float*)d_in[11];
    const float* fc2_w   = (const float*)d_in[12];
    const float* fc2_b   = (const float*)d_in[13];
    float* out = (float*)d_out;

    float *qkv, *attn, *x2, *hbuf;
    cudaGetSymbolAddress((void**)&qkv,  g_qkv);
    cudaGetSymbolAddress((void**)&attn, g_attn);
    cudaGetSymbolAddress((void**)&x2,   g_x2);
    cudaGetSymbolAddress((void**)&hbuf, g_h);

    const int fz_smem  = (128 * ASTR2 + 2 * 96 * 32) * 4;
    const int fc2_smem = 3 * (128 * ASTR + 96 * 32) * 4;
    cudaFuncSetAttribute(gemm_fz<EPI_QKV,  true,  true,  3>, cudaFuncAttributeMaxDynamicSharedMemorySize, fz_smem);
    cudaFuncSetAttribute(gemm_fz<EPI_PROJ, false, false, 1>, cudaFuncAttributeMaxDynamicSharedMemorySize, fz_smem);
    cudaFuncSetAttribute(gemm_fz<EPI_FC1,  true,  false, 4>, cudaFuncAttributeMaxDynamicSharedMemorySize, fz_smem);
    cudaFuncSetAttribute(gemm_fc2, cudaFuncAttributeMaxDynamicSharedMemorySize, fc2_smem);

    const int attn_smem = (256 * QSTR * 2 + 256 * 24 + 256 * PSTR + 512 + 64) * 4;
    cudaFuncSetAttribute(attn_mma, cudaFuncAttributeMaxDynamicSharedMemorySize, attn_smem);

    gemm_fz<EPI_QKV, true, true, 3><<<1024, 256, fz_smem>>>(
        x, qkv_w, qkv_b, nullptr, norm1_g, norm1_b, qkv);
    attn_mma<<<dim3(NWIN, NHEADS), 256, attn_smem>>>(qkv, attn);
    gemm_fz<EPI_PROJ, false, false, 1><<<1024, 256, fz_smem>>>(
        attn, proj_w, proj_b, x, nullptr, nullptr, x2);
    gemm_fz<EPI_FC1, true, false, 4><<<1024, 256, fz_smem>>>(
        x2, fc1_w, fc1_b, nullptr, norm2_g, norm2_b, hbuf);
    gemm_fc2<<<1024, 256, fc2_smem>>>(hbuf, fc2_w, fc2_b, x2, out);
}